// round 13
// baseline (speedup 1.0000x reference)
#include <cuda_runtime.h>

#define NB 128
#define THREADS 1024
#define NITER 60
#define TS 132                         // table stride: 132%32==4, float4-aligned, 8*TS%32==0

// float offsets into dynamic smem
#define OFF_W    0                     // w[2][128][128]            32768 floats
#define OFF_RT   32768                 // rowtab[2][32*TS]          2*4224
#define OFF_CT   (32768 + 8448)        // coltab[2][32*TS]          2*4224
#define OFF_SY   (32768 + 16896)       // sy[2][128]
#define OFF_SORT (OFF_SY + 256)        // sorted[2][128]
#define OFF_CSUM (OFF_SORT + 256)      // csum[2][2][128]
#define OFF_RANK (OFF_CSUM + 512)      // int rankp[2][4][128] (as 1024 float slots)
#define OFF_WS   (OFF_RANK + 1024)     // wsum[2][4], wcnt[2][4]
#define SMEM_FLOATS (OFF_WS + 16)

typedef unsigned long long ull;

__device__ __forceinline__ ull pk2(float lo, float hi) {
    ull r; asm("mov.b64 %0, {%1, %2};" : "=l"(r) : "f"(lo), "f"(hi)); return r;
}
__device__ __forceinline__ void upk2(ull v, float& lo, float& hi) {
    asm("mov.b64 {%0, %1}, %2;" : "=f"(lo), "=f"(hi) : "l"(v));
}
__device__ __forceinline__ ull padd2(ull a, ull b) {
    ull r; asm("add.rn.f32x2 %0, %1, %2;" : "=l"(r) : "l"(a), "l"(b)); return r;
}
__device__ __forceinline__ ull psub2(ull a, ull b) {
    ull r; asm("sub.rn.f32x2 %0, %1, %2;" : "=l"(r) : "l"(a), "l"(b)); return r;
}

extern __shared__ float smf[];

// ---- phase A for problem P (compile-time), z array Z (register array) ----
#define A_PHASE(P, Z) do {                                                          \
    const float* syP_ = smf + OFF_SY + (P) * NB;                                    \
    float4 sc4 = *reinterpret_cast<const float4*>(syP_ + 4 * lane);                 \
    float4 s4  = *reinterpret_cast<const float4*>(syP_ + rbase);                    \
    ull c2_0 = pk2(sc4.x, sc4.y), c2_1 = pk2(sc4.z, sc4.w);                         \
    const float syr_[4] = {s4.x, s4.y, s4.z, s4.w};                                 \
    ull ca0, ca1; float4 rv; float* rvp = &rv.x;                                    \
    _Pragma("unroll")                                                               \
    for (int r = 0; r < 4; ++r) {                                                   \
        float4 wr = *reinterpret_cast<const float4*>(                               \
            smf + OFF_W + (P) * NB * NB + (rbase + r) * NB + 4 * lane);             \
        ull s2 = pk2(syr_[r], syr_[r]);                                             \
        ull v0 = padd2(Z[r][0], psub2(s2, c2_0));                                   \
        float ax, ay; upk2(v0, ax, ay);                                             \
        ax = fminf(fmaxf(ax, -wr.x), wr.x);                                         \
        ay = fminf(fmaxf(ay, -wr.y), wr.y);                                         \
        ull zz0 = pk2(ax, ay); Z[r][0] = zz0;                                       \
        ull v1 = padd2(Z[r][1], psub2(s2, c2_1));                                   \
        float bx, by; upk2(v1, bx, by);                                             \
        bx = fminf(fmaxf(bx, -wr.z), wr.z);                                         \
        by = fminf(fmaxf(by, -wr.w), wr.w);                                         \
        ull zz1 = pk2(bx, by); Z[r][1] = zz1;                                       \
        if (r == 0) { ca0 = zz0; ca1 = zz1; }                                       \
        else        { ca0 = padd2(ca0, zz0); ca1 = padd2(ca1, zz1); }               \
        ull rs2 = padd2(zz0, zz1); float rl, rh; upk2(rs2, rl, rh);                 \
        rvp[r] = rl + rh;                                                           \
    }                                                                               \
    *reinterpret_cast<float4*>(smf + OFF_RT + (P) * 4224 + lane * TS + 4 * warp) = rv; \
    { float4 cv; upk2(ca0, cv.x, cv.y); upk2(ca1, cv.z, cv.w);                      \
      *reinterpret_cast<float4*>(smf + OFF_CT + (P) * 4224 + warp * TS + 4 * lane) = cv; } \
} while (0)

// ---- phase B for problem P: 8 threads per j, contribs {g+8k}, 3 shuffles ----
#define B_PHASE(P, XQ) do {                                                         \
    const float* rrd_ = smf + OFF_RT + (P) * 4224 + g * TS + j;                     \
    const float* crd_ = smf + OFF_CT + (P) * 4224 + g * TS + j;                     \
    float t0_ = (crd_[0] - rrd_[0]) + (crd_[8 * TS] - rrd_[8 * TS]);                \
    float t1_ = (crd_[16 * TS] - rrd_[16 * TS]) + (crd_[24 * TS] - rrd_[24 * TS]);  \
    float d_ = t0_ + t1_;                                                           \
    d_ += __shfl_xor_sync(0xffffffffu, d_, 1);                                      \
    d_ += __shfl_xor_sync(0xffffffffu, d_, 2);                                      \
    d_ += __shfl_xor_sync(0xffffffffu, d_, 4);                                      \
    if (g == 0) smf[OFF_SY + (P) * NB + j] = step * ((XQ) + d_);                    \
} while (0)

__global__ void __launch_bounds__(THREADS, 1)
gfusedmax_kernel(const float* __restrict__ x,
                 const float* __restrict__ A,
                 float* __restrict__ out)
{
    const int tid   = threadIdx.x;
    const int lane  = tid & 31;
    const int warp  = tid >> 5;
    const int rbase = warp * 4;            // warp w owns rows 4w..4w+3; lane L owns cols 4L..4L+3
    const int pb0   = blockIdx.x * 2;      // this CTA solves problems pb0, pb0+1

    const float step = 1.0f / 256.0f;

    // ---- stream both problems' clip bounds into smem (coalesced float4) ----
    {
        float4* wdst = reinterpret_cast<float4*>(smf + OFF_W);
        const float4* wsrc = reinterpret_cast<const float4*>(A + (size_t)pb0 * NB * NB);
        #pragma unroll
        for (int i = 0; i < 8; ++i)        // 2 * 16384 floats = 8192 float4
            wdst[tid + i * 1024] = wsrc[tid + i * 1024];
    }

    // ---- phase-B identity ----
    const int j = tid >> 3;
    const int g = tid & 7;
    const float xq0 = x[(size_t)pb0 * NB + j];
    const float xq1 = x[(size_t)(pb0 + 1) * NB + j];

    // z state for BOTH problems, packed, init 0 (original domain, clip +-w)
    ull za[4][2], zb[4][2];
    #pragma unroll
    for (int r = 0; r < 4; ++r) { za[r][0] = za[r][1] = 0ULL; zb[r][0] = zb[r][1] = 0ULL; }

    if (g == 0) {
        smf[OFF_SY + j]      = step * xq0;
        smf[OFF_SY + NB + j] = step * xq1;
    }
    __syncthreads();

    // ---- pipelined schedule: 1 barrier per phase, 2 problems in flight ----
    A_PHASE(0, za);
    __syncthreads();
    #pragma unroll 1
    for (int ph = 1; ph <= 2 * NITER - 1; ++ph) {
        if (ph & 1) { B_PHASE(0, xq0); A_PHASE(1, zb); }
        else        { B_PHASE(1, xq1); A_PHASE(0, za); }
        __syncthreads();
    }
    B_PHASE(1, xq1);
    __syncthreads();

    // ================= tail: sparsemax for both problems in parallel =========
    const int pt = tid >> 9;               // problem slot 0/1
    const int lt = tid & 511;
    const int i  = lt & 127;
    const int gg = lt >> 7;                // 0..3, 32 comparisons each
    float* syP   = smf + OFF_SY   + pt * NB;
    float* sortP = smf + OFF_SORT + pt * NB;
    float* csumP = smf + OFF_CSUM + pt * 256;
    int*   rankP = reinterpret_cast<int*>(smf + OFF_RANK) + pt * 512;
    float* wsP   = smf + OFF_WS + pt * 4;
    float* wcP   = smf + OFF_WS + 8 + pt * 4;

    // rank sort (branch-free, deterministic; sy = step*y, positive scale preserves order)
    {
        float vi = syP[i];
        int rp = 0;
        #pragma unroll
        for (int jj = 0; jj < 32; ++jj) {
            int jc = gg * 32 + jj;
            float uj = syP[jc];
            rp += (uj > vi) || (uj == vi && jc < i);
        }
        rankP[gg * NB + i] = rp;
    }
    __syncthreads();
    float yv = 0.0f;
    if (lt < NB) {
        yv = syP[i] * 256.0f;              // exact (exponent-only)
        int rank = (rankP[i] + rankP[NB + i]) + (rankP[2 * NB + i] + rankP[3 * NB + i]);
        sortP[rank] = yv;                  // descending
    }
    __syncthreads();

    // inclusive scan (Hillis-Steele, ping-pong)
    if (lt < NB) csumP[i] = sortP[i];
    __syncthreads();
    int src = 0;
    for (int off = 1; off < NB; off <<= 1) {
        if (lt < NB) {
            float vv = csumP[src * NB + i];
            if (i >= off) vv += csumP[src * NB + i - off];
            csumP[(1 - src) * NB + i] = vv;
        }
        __syncthreads();
        src = 1 - src;
    }

    // mask + deterministic (sum, count) funnel (full warps: 0-3 / 16-19)
    if (lt < NB) {
        float s  = sortP[i];
        float cu = csumP[src * NB + i];
        float k  = (float)(i + 1);
        bool  m  = (1.0f + k * s > cu);
        float sv = m ? s : 0.0f;
        float sc = m ? 1.0f : 0.0f;
        #pragma unroll
        for (int sft = 16; sft > 0; sft >>= 1) {
            sv += __shfl_xor_sync(0xffffffffu, sv, sft);
            sc += __shfl_xor_sync(0xffffffffu, sc, sft);
        }
        if (lane == 0) { wsP[lt >> 5] = sv; wcP[lt >> 5] = sc; }
    }
    __syncthreads();

    if (lt < NB) {
        float ssum = (wsP[0] + wsP[1]) + (wsP[2] + wsP[3]);
        float scnt = (wcP[0] + wcP[1]) + (wcP[2] + wcP[3]);
        float tau  = (ssum - 1.0f) / scnt;
        out[(size_t)(pb0 + pt) * NB + i] = fmaxf(yv - tau, 0.0f);
    }
}

extern "C" void kernel_launch(void* const* d_in, const int* in_sizes, int n_in,
                              void* d_out, int out_size)
{
    const float* x = (const float*)d_in[0];   // [B, 128]
    const float* A = (const float*)d_in[1];   // [B, 128, 128]
    float* out = (float*)d_out;               // [B, 128] float32

    int B = in_sizes[0] / NB;                 // 4096
    size_t smem_bytes = (size_t)SMEM_FLOATS * sizeof(float);   // ~202 KB
    cudaFuncSetAttribute(gfusedmax_kernel,
                         cudaFuncAttributeMaxDynamicSharedMemorySize, (int)smem_bytes);
    gfusedmax_kernel<<<B / 2, THREADS, smem_bytes>>>(x, A, out);
}

// round 14
// speedup vs baseline: 1.2934x; 1.2934x over previous
#include <cuda_runtime.h>

#define NB 128
#define THREADS 512
#define NITER 60
#define TS 132

// float offsets into dynamic smem (per CTA)
#define OFF_W    0                      // w[128][128]        16384
#define OFF_RT   16384                  // rowtab[32*TS]       4224
#define OFF_CT   20608                  // coltab[16*TS]       2112
#define OFF_SY   22720                  // sy[128]
#define OFF_SORT 22848                  // sorted[128]
#define OFF_CSUM 22976                  // csum[2][128]
#define OFF_RANK 23232                  // int rankp[4][128]
#define OFF_WS   23744                  // wsum[4], wcnt[4]
#define SMEM_FLOATS 23752               // ~92.8 KB

typedef unsigned long long ull;

__device__ __forceinline__ ull pk2(float lo, float hi) {
    ull r; asm("mov.b64 %0, {%1, %2};" : "=l"(r) : "f"(lo), "f"(hi)); return r;
}
__device__ __forceinline__ void upk2(ull v, float& lo, float& hi) {
    asm("mov.b64 {%0, %1}, %2;" : "=f"(lo), "=f"(hi) : "l"(v));
}
__device__ __forceinline__ ull padd2(ull a, ull b) {
    ull r; asm("add.rn.f32x2 %0, %1, %2;" : "=l"(r) : "l"(a), "l"(b)); return r;
}
__device__ __forceinline__ ull psub2(ull a, ull b) {
    ull r; asm("sub.rn.f32x2 %0, %1, %2;" : "=l"(r) : "l"(a), "l"(b)); return r;
}

extern __shared__ float smf[];

__global__ void __launch_bounds__(THREADS, 2)
gfusedmax_kernel(const float* __restrict__ x,
                 const float* __restrict__ A,
                 float* __restrict__ out)
{
    const int b     = blockIdx.x;
    const int tid   = threadIdx.x;
    const int lane  = tid & 31;
    const int warp  = tid >> 5;            // 16 warps; warp w owns rows 8w..8w+7
    const float step = 1.0f / 256.0f;      // lane L owns cols 4L..4L+3

    // ---- stream this problem's clip bounds into smem (coalesced float4) ----
    {
        float4* wdst = reinterpret_cast<float4*>(smf + OFF_W);
        const float4* wsrc = reinterpret_cast<const float4*>(A + (size_t)b * NB * NB);
        #pragma unroll
        for (int i = 0; i < 8; ++i)        // 16384 floats = 4096 float4
            wdst[tid + i * 512] = wsrc[tid + i * 512];
    }

    // ---- z state: 8 rows x 4 cols packed, init 0 ----
    ull z2[8][2];
    #pragma unroll
    for (int r = 0; r < 8; ++r) { z2[r][0] = 0ULL; z2[r][1] = 0ULL; }

    // ---- phase-B identity: j0 = tid>>3 in [0,64), also handles j1 = j0+64 ----
    const int j0 = tid >> 3;
    const int g  = tid & 7;
    const int j1 = j0 + 64;
    const float xq0 = x[(size_t)b * NB + j0];
    const float xq1 = x[(size_t)b * NB + j1];

    // pointers
    const float* wp  = smf + OFF_W + warp * (8 * NB) + 4 * lane;   // + r*128 per row
    float* rtw = smf + OFF_RT + lane * TS + 8 * warp;              // rowtab[lane][8w+r]
    float* ctw = smf + OFF_CT + warp * TS + 4 * lane;              // coltab[warp][4L..]
    const float* rrd = smf + OFF_RT + g * TS;                      // + 8k*TS + j
    const float* crd = smf + OFF_CT + g * TS;                      // + 8k*TS + j
    float* syp = smf + OFF_SY;

    if (g == 0) { syp[j0] = step * xq0; syp[j1] = step * xq1; }
    __syncthreads();

    // ---- 60 projected-gradient iterations, 2 bars each (hidden by 2 CTAs/SM) ----
    #pragma unroll 1
    for (int it = 0; it < NITER; ++it) {
        // ===== phase A =====
        float4 sc4 = *reinterpret_cast<const float4*>(syp + 4 * lane);   // cols
        float4 sra = *reinterpret_cast<const float4*>(syp + 8 * warp);   // rows 8w..8w+3
        float4 srb = *reinterpret_cast<const float4*>(syp + 8 * warp + 4);
        ull c2_0 = pk2(sc4.x, sc4.y);
        ull c2_1 = pk2(sc4.z, sc4.w);
        const float syr[8] = {sra.x, sra.y, sra.z, sra.w, srb.x, srb.y, srb.z, srb.w};

        ull ca0, ca1;
        float4 rva, rvb;
        float* rvap = &rva.x;
        float* rvbp = &rvb.x;

        #pragma unroll
        for (int r = 0; r < 8; ++r) {
            float4 wr = *reinterpret_cast<const float4*>(wp + r * NB);   // LDS.128
            ull s2 = pk2(syr[r], syr[r]);
            // cols (4L, 4L+1)
            ull v0 = padd2(z2[r][0], psub2(s2, c2_0));
            float ax, ay; upk2(v0, ax, ay);
            ax = fminf(fmaxf(ax, -wr.x), wr.x);
            ay = fminf(fmaxf(ay, -wr.y), wr.y);
            ull zz0 = pk2(ax, ay);
            z2[r][0] = zz0;
            // cols (4L+2, 4L+3)
            ull v1 = padd2(z2[r][1], psub2(s2, c2_1));
            float bx, by; upk2(v1, bx, by);
            bx = fminf(fmaxf(bx, -wr.z), wr.z);
            by = fminf(fmaxf(by, -wr.w), wr.w);
            ull zz1 = pk2(bx, by);
            z2[r][1] = zz1;
            // accumulate
            if (r == 0) { ca0 = zz0; ca1 = zz1; }
            else        { ca0 = padd2(ca0, zz0); ca1 = padd2(ca1, zz1); }
            ull rs2 = padd2(zz0, zz1);
            float rl, rh; upk2(rs2, rl, rh);
            if (r < 4) rvap[r] = rl + rh; else rvbp[r - 4] = rl + rh;
        }

        // packed partial stores (quarter-warp conflict-free)
        *reinterpret_cast<float4*>(rtw)     = rva;
        *reinterpret_cast<float4*>(rtw + 4) = rvb;
        {
            float4 cv;
            upk2(ca0, cv.x, cv.y);
            upk2(ca1, cv.z, cv.w);
            *reinterpret_cast<float4*>(ctw) = cv;
        }
        __syncthreads();

        // ===== phase B: 8 threads per j, each thread covers j0 and j1 =====
        float d0, d1;
        {
            float r0 = (rrd[0 * 8 * TS + j0] + rrd[1 * 8 * TS + j0])
                     + (rrd[2 * 8 * TS + j0] + rrd[3 * 8 * TS + j0]);
            float c0 = crd[0 * 8 * TS + j0] + crd[1 * 8 * TS + j0];
            d0 = c0 - r0;
            float r1 = (rrd[0 * 8 * TS + j1] + rrd[1 * 8 * TS + j1])
                     + (rrd[2 * 8 * TS + j1] + rrd[3 * 8 * TS + j1]);
            float c1 = crd[0 * 8 * TS + j1] + crd[1 * 8 * TS + j1];
            d1 = c1 - r1;
        }
        d0 += __shfl_xor_sync(0xffffffffu, d0, 1);
        d1 += __shfl_xor_sync(0xffffffffu, d1, 1);
        d0 += __shfl_xor_sync(0xffffffffu, d0, 2);
        d1 += __shfl_xor_sync(0xffffffffu, d1, 2);
        d0 += __shfl_xor_sync(0xffffffffu, d0, 4);
        d1 += __shfl_xor_sync(0xffffffffu, d1, 4);
        if (g == 0) {
            syp[j0] = step * (xq0 + d0);
            syp[j1] = step * (xq1 + d1);
        }
        __syncthreads();
    }

    // ================= tail: sparsemax (512 threads, one problem) =============
    float* sortP = smf + OFF_SORT;
    float* csumP = smf + OFF_CSUM;
    int*   rankP = reinterpret_cast<int*>(smf + OFF_RANK);
    float* wsP   = smf + OFF_WS;
    float* wcP   = smf + OFF_WS + 4;

    // rank sort: 4 groups x 32 comparisons (branch-free, deterministic)
    {
        int i  = tid & 127;
        int gg = tid >> 7;                 // 0..3
        float vi = syp[i];
        int rp = 0;
        #pragma unroll
        for (int jj = 0; jj < 32; ++jj) {
            int jc = gg * 32 + jj;
            float uj = syp[jc];
            rp += (uj > vi) || (uj == vi && jc < i);
        }
        rankP[gg * NB + i] = rp;
    }
    __syncthreads();
    float yv = 0.0f;
    if (tid < NB) {
        yv = syp[tid] * 256.0f;            // exact (exponent-only)
        int rank = (rankP[tid] + rankP[NB + tid]) + (rankP[2 * NB + tid] + rankP[3 * NB + tid]);
        sortP[rank] = yv;                  // descending
    }
    __syncthreads();

    // inclusive scan (Hillis-Steele, ping-pong)
    if (tid < NB) csumP[tid] = sortP[tid];
    __syncthreads();
    int src = 0;
    for (int off = 1; off < NB; off <<= 1) {
        if (tid < NB) {
            float vv = csumP[src * NB + tid];
            if (tid >= off) vv += csumP[src * NB + tid - off];
            csumP[(1 - src) * NB + tid] = vv;
        }
        __syncthreads();
        src = 1 - src;
    }

    // mask + deterministic (sum, count) funnel (warps 0-3)
    if (tid < NB) {
        float s  = sortP[tid];
        float cu = csumP[src * NB + tid];
        float k  = (float)(tid + 1);
        bool  m  = (1.0f + k * s > cu);
        float sv = m ? s : 0.0f;
        float sc = m ? 1.0f : 0.0f;
        #pragma unroll
        for (int sft = 16; sft > 0; sft >>= 1) {
            sv += __shfl_xor_sync(0xffffffffu, sv, sft);
            sc += __shfl_xor_sync(0xffffffffu, sc, sft);
        }
        if (lane == 0) { wsP[tid >> 5] = sv; wcP[tid >> 5] = sc; }
    }
    __syncthreads();

    if (tid < NB) {
        float ssum = (wsP[0] + wsP[1]) + (wsP[2] + wsP[3]);
        float scnt = (wcP[0] + wcP[1]) + (wcP[2] + wcP[3]);
        float tau  = (ssum - 1.0f) / scnt;
        out[(size_t)b * NB + tid] = fmaxf(yv - tau, 0.0f);
    }
}

extern "C" void kernel_launch(void* const* d_in, const int* in_sizes, int n_in,
                              void* d_out, int out_size)
{
    const float* x = (const float*)d_in[0];   // [B, 128]
    const float* A = (const float*)d_in[1];   // [B, 128, 128]
    float* out = (float*)d_out;               // [B, 128] float32

    int B = in_sizes[0] / NB;                 // 4096
    size_t smem_bytes = (size_t)SMEM_FLOATS * sizeof(float);   // ~92.8 KB
    cudaFuncSetAttribute(gfusedmax_kernel,
                         cudaFuncAttributeMaxDynamicSharedMemorySize, (int)smem_bytes);
    gfusedmax_kernel<<<B, THREADS, smem_bytes>>>(x, A, out);
}